// round 15
// baseline (speedup 1.0000x reference)
#include <cuda_runtime.h>
#include <cstdint>

#define Bn   64
#define Nn   512
#define Tt   8
#define DINd 2
#define Hh   256
#define Ll   3
#define Ee   8192
#define Mm   128
#define Pout 24
#define EPSf 1e-5f

// ---------------- scratch (allocation-free) ----------------
__device__ float g_h    [Bn*Nn*Hh];
__device__ float g_hs   [Bn*Nn*Hh];    // h + relu(BN(hc)) row-major (decoder input)
__device__ float g_hsT  [Bn*Hh*Nn];    // encoder output^T (layer-0 S1 B operand)
__device__ float g_hcT  [Bn*Hh*Nn];    // conv output^T pre-BN (written by S3)
__device__ float g_Yp   [2*Bn*Mm*Hh];  // S1 split-K partials (consumed by S2)
__device__ float g_ZT   [Bn*Hh*Mm];    // (Y @ theta)^T, fp32
__device__ float g_Hc   [Bn*Nn*Mm];    // raw integer counts (tf32-exact)
__device__ float g_HcT  [Bn*Mm*Nn];    // raw integer counts (tf32-exact)
__device__ float g_thT  [Ll*Hh*Hh];    // theta^T, fp32
__device__ float g_invb [Bn*Mm];
__device__ float g_invd [Bn*Nn];
__device__ float g_sum  [Bn*Hh];
__device__ float g_sq   [Bn*Hh];
__device__ float g_bnA  [Bn*Hh];
__device__ float g_bnB  [Bn*Hh];

// ================= helpers =================
__device__ __forceinline__ uint32_t smem_u32(const void* p) {
    uint32_t a;
    asm("{ .reg .u64 t; cvta.to.shared.u64 t, %1; cvt.u32.u64 %0, t; }" : "=r"(a) : "l"(p));
    return a;
}
__device__ __forceinline__ uint32_t lo_tf32(uint32_t vbits) {
    float hi = __uint_as_float(vbits & 0xffffe000u);
    return __float_as_uint(__uint_as_float(vbits) - hi);
}
#define CP16(dst, src) asm volatile("cp.async.cg.shared.global [%0], [%1], 16;" :: "r"(dst), "l"(src) : "memory")
#define CPCOMMIT()     asm volatile("cp.async.commit_group;" ::: "memory")
#define CPWAIT1()      asm volatile("cp.async.wait_group 1;" ::: "memory")

__device__ __forceinline__ void ldsm4(uint32_t* r, uint32_t addr) {
    asm volatile("ldmatrix.sync.aligned.m8n8.x4.shared.b16 {%0,%1,%2,%3}, [%4];"
        : "=r"(r[0]), "=r"(r[1]), "=r"(r[2]), "=r"(r[3]) : "r"(addr));
}
__device__ __forceinline__ void mma_tf32(float* c, const uint32_t* a, const uint32_t* b) {
    asm volatile(
        "mma.sync.aligned.m16n8k8.row.col.f32.tf32.tf32.f32 "
        "{%0,%1,%2,%3}, {%4,%5,%6,%7}, {%8,%9}, {%0,%1,%2,%3};"
        : "+f"(c[0]), "+f"(c[1]), "+f"(c[2]), "+f"(c[3])
        : "r"(a[0]), "r"(a[1]), "r"(a[2]), "r"(a[3]), "r"(b[0]), "r"(b[1]));
}

// ================= error-compensated tf32 mma.sync GEMM =================
// Block 128x64 (MxN), BK=32, 8 warps (2m x 4n), warp tile 64x16; ldmatrix loads.
// hi operand = raw fp32 bits (HW truncates), lo = exact truncation residual.
// SPLITA: add A-lo term. COMBINE: B := (B + B[bOff2]) * rowscaleB[row].
// BNB: B := relu(B*bnA[row]+bnB[row]). TRANSC: smem-staged transposed C.
// STATS/RS/BIAS: compile-time epilogue features.
#define AFL 4096
#define BFL 2048
#define O_B  8192
#define O_B2 12288

template<int SPLITA, int COMBINE, int BNB, int TRANSC, int STATS, int RS, int BIAS>
__global__ void __launch_bounds__(256, 3)
k_mma2(const float* __restrict__ Ag, const float* __restrict__ Bg,
       float* __restrict__ Cg,
       const float* __restrict__ rowscale, const float* __restrict__ bias,
       const float* __restrict__ rowscaleB, long bOff2,
       const float* __restrict__ bnA, const float* __restrict__ bnB,
       int K, int lda, int ldb, int N, int M,
       long sA, long sB, long sC, int zstats,
       int koffY, long cOffY) {
    extern __shared__ float sm[];
    uint32_t sbase = smem_u32(sm);

    int tid = threadIdx.x, lane = tid & 31, wid = tid >> 5;
    int wm = wid >> 2, wn = wid & 3;           // 2 x 4 warp grid, warp tile 64x16
    int col0 = blockIdx.x * 64;
    int row0, k_base;
    long cadd;
    if (koffY) { row0 = 0; k_base = blockIdx.y * koffY; cadd = (long)blockIdx.y * cOffY; }
    else       { row0 = blockIdx.y * 128; k_base = 0; cadd = 0; }
    int z = blockIdx.z;

    if (zstats && blockIdx.y == 0 && tid < 64) {
        g_sum[z * Hh + col0 + tid] = 0.f;
        g_sq [z * Hh + col0 + tid] = 0.f;
    }

    const float* A  = Ag + (size_t)z * sA + k_base;
    const float* B  = Bg + (size_t)z * sB + k_base;
    const float* B2 = COMBINE ? (Bg + bOff2 + (size_t)z * sB + k_base) : nullptr;
    float* C = Cg + (size_t)z * sC + cadd;

    int cr = tid >> 3;                 // 0..31
    int cc = (tid & 7) * 4;

    float acc[4][2][4];
#pragma unroll
    for (int i = 0; i < 4; i++)
#pragma unroll
        for (int j = 0; j < 2; j++)
#pragma unroll
            for (int q = 0; q < 4; q++) acc[i][j][q] = 0.f;

    int nkb = K >> 5;
    int g = lane >> 2, t = lane & 3;

    float rsB[2], bAc[2], bBc[2];
    if (COMBINE) {
#pragma unroll
        for (int nf = 0; nf < 2; nf++)
            rsB[nf] = rowscaleB[(size_t)z * Mm + col0 + wn * 16 + nf * 8 + g];
    }
    if (BNB) {
#pragma unroll
        for (int nf = 0; nf < 2; nf++) {
            int idx = z * Hh + col0 + wn * 16 + nf * 8 + g;
            bAc[nf] = bnA[idx];
            bBc[nf] = bnB[idx];
        }
    }

    // ldmatrix per-lane addressing
    int lrow = lane & 7;
    int lsub = lane >> 3;
    uint32_t rm4  = (uint32_t)lrow << 4;
    uint32_t cb4A = (uint32_t)(lsub >> 1) << 4;
    uint32_t cb4B = (uint32_t)(lsub & 1) << 4;
    uint32_t aAddr[4], bAddr;
#pragma unroll
    for (int mf = 0; mf < 4; mf++)
        aAddr[mf] = sbase + (uint32_t)((wm * 64 + mf * 16 + ((lsub & 1) << 3) + lrow) << 7);
    bAddr = sbase + O_B * 4 + (uint32_t)((wn * 16 + (lsub >> 1) * 8 + lrow) << 7);

#pragma unroll
    for (int s = 0; s < 2; s++) {
        int kk = s * 32;
#pragma unroll
        for (int i = 0; i < 4; i++) {             // A: 128 rows, 256 threads
            int rr = cr + i * 32;
            uint32_t so = (uint32_t)(s * AFL + rr * 32 + (cc ^ ((rr & 7) * 4))) * 4;
            CP16(sbase + so, A + (size_t)(row0 + rr) * lda + kk + cc);
        }
#pragma unroll
        for (int i = 0; i < 2; i++) {             // B: 64 rows
            int rr = cr + i * 32;
            uint32_t sw = (uint32_t)(rr * 32 + (cc ^ ((rr & 7) * 4)));
            size_t gb = (size_t)(col0 + rr) * ldb + kk + cc;
            CP16(sbase + (uint32_t)(O_B + s * BFL + sw) * 4, B + gb);
            if (COMBINE) CP16(sbase + (uint32_t)(O_B2 + s * BFL + sw) * 4, B2 + gb);
        }
        CPCOMMIT();
    }

    for (int kb = 0; kb < nkb; kb++) {
        int s = kb & 1;
        CPWAIT1();
        __syncthreads();
        uint32_t aOffS = (uint32_t)(s * AFL) * 4;
        uint32_t bOffS = (uint32_t)(s * BFL) * 4;

#pragma unroll
        for (int ks = 0; ks < 4; ks++) {
            uint32_t ka  = (((uint32_t)ks << 5) + cb4A) ^ rm4;
            uint32_t kbo = (((uint32_t)ks << 5) + cb4B) ^ rm4;
            uint32_t a[4][4], bR[2][2], bl[2][2];
#pragma unroll
            for (int mf = 0; mf < 4; mf++)
                ldsm4(a[mf], aAddr[mf] + aOffS + ka);
            {
                uint32_t r[4];
                ldsm4(r, bAddr + bOffS + kbo);
                bR[0][0] = r[0]; bR[0][1] = r[1]; bR[1][0] = r[2]; bR[1][1] = r[3];
            }
            if (COMBINE) {
                uint32_t r[4];
                ldsm4(r, bAddr + (O_B2 - O_B) * 4 + bOffS + kbo);
#pragma unroll
                for (int nf = 0; nf < 2; nf++)
#pragma unroll
                    for (int q = 0; q < 2; q++) {
                        float u = (__uint_as_float(bR[nf][q]) + __uint_as_float(r[nf*2+q])) * rsB[nf];
                        bR[nf][q] = __float_as_uint(u);
                    }
            }
            if (BNB) {
#pragma unroll
                for (int nf = 0; nf < 2; nf++)
#pragma unroll
                    for (int q = 0; q < 2; q++) {
                        float u = fmaxf(fmaf(__uint_as_float(bR[nf][q]), bAc[nf], bBc[nf]), 0.f);
                        bR[nf][q] = __float_as_uint(u);
                    }
            }
#pragma unroll
            for (int nf = 0; nf < 2; nf++) {
                bl[nf][0] = lo_tf32(bR[nf][0]);
                bl[nf][1] = lo_tf32(bR[nf][1]);
            }
#pragma unroll
            for (int mf = 0; mf < 4; mf++)
#pragma unroll
                for (int nf = 0; nf < 2; nf++)
                    mma_tf32(acc[mf][nf], a[mf], bR[nf]);
#pragma unroll
            for (int mf = 0; mf < 4; mf++)
#pragma unroll
                for (int nf = 0; nf < 2; nf++)
                    mma_tf32(acc[mf][nf], a[mf], bl[nf]);
            if (SPLITA) {
                uint32_t al[4][4];
#pragma unroll
                for (int mf = 0; mf < 4; mf++)
#pragma unroll
                    for (int q = 0; q < 4; q++)
                        al[mf][q] = lo_tf32(a[mf][q]);
#pragma unroll
                for (int mf = 0; mf < 4; mf++)
#pragma unroll
                    for (int nf = 0; nf < 2; nf++)
                        mma_tf32(acc[mf][nf], al[mf], bR[nf]);
            }
        }
        __syncthreads();

        if (kb + 2 < nkb) {
            int kk = (kb + 2) * 32;
#pragma unroll
            for (int i = 0; i < 4; i++) {
                int rr = cr + i * 32;
                uint32_t so = (uint32_t)(s * AFL + rr * 32 + (cc ^ ((rr & 7) * 4))) * 4;
                CP16(sbase + so, A + (size_t)(row0 + rr) * lda + kk + cc);
            }
#pragma unroll
            for (int i = 0; i < 2; i++) {
                int rr = cr + i * 32;
                uint32_t sw = (uint32_t)(rr * 32 + (cc ^ ((rr & 7) * 4)));
                size_t gb = (size_t)(col0 + rr) * ldb + kk + cc;
                CP16(sbase + (uint32_t)(O_B + s * BFL + sw) * 4, B + gb);
                if (COMBINE) CP16(sbase + (uint32_t)(O_B2 + s * BFL + sw) * 4, B2 + gb);
            }
        }
        CPCOMMIT();
    }

    // ---------------- epilogue ----------------
    const float* rsb = RS ? (rowscale + (size_t)z * M) : nullptr;
    float cs[STATS ? 4 : 1], cq[STATS ? 4 : 1];
    if (STATS) {
#pragma unroll
        for (int i = 0; i < 4; i++) { cs[i] = 0.f; cq[i] = 0.f; }
    }
    if (TRANSC) __syncthreads();

#pragma unroll
    for (int mf = 0; mf < 4; mf++) {
        int rl = wm * 64 + mf * 16 + g;
        int rr = row0 + rl;
        float rs0 = RS ? rsb[rr]     : 1.f;
        float rs1 = RS ? rsb[rr + 8] : 1.f;
#pragma unroll
        for (int nf = 0; nf < 2; nf++) {
            int cl  = wn * 16 + nf * 8 + t * 2;
            int ccg = col0 + cl;
            float c0 = acc[mf][nf][0] * rs0, c1 = acc[mf][nf][1] * rs0;
            float c2 = acc[mf][nf][2] * rs1, c3 = acc[mf][nf][3] * rs1;
            if (BIAS) {
                float b0 = bias[ccg], b1 = bias[ccg + 1];
                c0 += b0; c1 += b1; c2 += b0; c3 += b1;
            }
            if (STATS) {
                cs[nf*2]   += c0 + c2;  cs[nf*2+1] += c1 + c3;
                cq[nf*2]   += c0*c0 + c2*c2;
                cq[nf*2+1] += c1*c1 + c3*c3;
            }
            if (TRANSC) {
                sm[cl       * 132 + rl    ] = c0;
                sm[(cl + 1) * 132 + rl    ] = c1;
                sm[cl       * 132 + rl + 8] = c2;
                sm[(cl + 1) * 132 + rl + 8] = c3;
            } else {
                *reinterpret_cast<float2*>(&C[(size_t)rr * N + ccg])       = make_float2(c0, c1);
                *reinterpret_cast<float2*>(&C[(size_t)(rr + 8) * N + ccg]) = make_float2(c2, c3);
            }
        }
    }
    if (TRANSC) {
        __syncthreads();
        for (int i = tid; i < 64 * 32; i += 256) {
            int h  = i >> 5;
            int n4 = (i & 31) << 2;
            float4 v = *reinterpret_cast<float4*>(&sm[h * 132 + n4]);
            *reinterpret_cast<float4*>(&C[(size_t)(col0 + h) * N + row0 + n4]) = v;
        }
    }
    if (STATS) {
#pragma unroll
        for (int off = 4; off <= 16; off <<= 1) {
#pragma unroll
            for (int i = 0; i < 4; i++) {
                cs[i] += __shfl_xor_sync(0xffffffffu, cs[i], off);
                cq[i] += __shfl_xor_sync(0xffffffffu, cq[i], off);
            }
        }
        if (g == 0) {
#pragma unroll
            for (int nf = 0; nf < 2; nf++) {
#pragma unroll
                for (int j = 0; j < 2; j++) {
                    int ccg = col0 + wn * 16 + nf * 8 + t * 2 + j;
                    atomicAdd(&g_sum[z * Hh + ccg], cs[nf*2+j]);
                    atomicAdd(&g_sq [z * Hh + ccg], cq[nf*2+j]);
                }
            }
        }
    }
}

// ---------------- encoder ----------------
__global__ void k_encoder(const float* __restrict__ obs,
                          const float* __restrict__ Wenc,
                          const float* __restrict__ benc) {
    int bn = blockIdx.x;
    int h  = threadIdx.x;
    int b  = bn >> 9, n = bn & (Nn - 1);
    __shared__ float srow[Tt*DINd];
    if (h < Tt*DINd) srow[h] = obs[bn*Tt*DINd + h];
    __syncthreads();
    float w0 = Wenc[h], w1 = Wenc[Hh + h], bb = benc[h];
    float acc = 0.f;
#pragma unroll
    for (int t = 0; t < Tt; t++) {
        float v = fmaf(srow[2*t], w0, fmaf(srow[2*t+1], w1, bb));
        acc += fmaxf(v, 0.f);
    }
    float r = acc * (1.f / Tt);
    g_h[(size_t)bn*Hh + h] = r;
    g_hsT[((size_t)b*Hh + h)*Nn + n] = r;
}

// ---------------- fused incidence build: smem byte counts -> Hc/HcT/invb/invd ----------------
// One CTA per batch. 64KB dynamic smem holds packed uint8 counts [n][m].
__global__ void __launch_bounds__(256) k_build2(const int* __restrict__ idx) {
    extern __shared__ uint32_t scnt[];           // 16384 words = 64KB
    __shared__ int sdn[Nn];
    __shared__ int sdm[Mm];
    int b = blockIdx.x, tid = threadIdx.x;
    for (int i = tid; i < 16384; i += 256) scnt[i] = 0u;
    for (int i = tid; i < Nn; i += 256) sdn[i] = 0;
    if (tid < Mm) sdm[tid] = 0;
    __syncthreads();
    const int* nodes = idx + b*2*Ee;
    const int* edges = nodes + Ee;
    for (int e = tid; e < Ee; e += 256) {
        int n = nodes[e], m = edges[e];
        int j = n * Mm + m;
        atomicAdd(&scnt[j >> 2], 1u << ((j & 3) * 8));
        atomicAdd(&sdn[n], 1);
        atomicAdd(&sdm[m], 1);
    }
    __syncthreads();
    if (tid < Mm) g_invb[b*Mm + tid] = 1.f / fmaxf((float)sdm[tid], 1.f);
    for (int i = tid; i < Nn; i += 256) g_invd[b*Nn + i] = 1.f / fmaxf((float)sdn[i], 1.f);
    float* hc  = g_Hc  + (size_t)b * Nn * Mm;
    float* hct = g_HcT + (size_t)b * Mm * Nn;
    for (int i = tid; i < Nn*Mm; i += 256)
        hc[i] = (float)((scnt[i >> 2] >> ((i & 3) * 8)) & 0xffu);
    for (int i = tid; i < Mm*Nn; i += 256) {
        int m = i >> 9, n = i & (Nn - 1);
        int j = n * Mm + m;
        hct[i] = (float)((scnt[j >> 2] >> ((j & 3) * 8)) & 0xffu);
    }
}

// ---------------- theta transpose ----------------
__global__ void k_trans_theta(const float* __restrict__ thetas) {
    __shared__ float t[32][33];
    int l  = blockIdx.z;
    int x0 = blockIdx.x * 32, y0 = blockIdx.y * 32;
    int tx = threadIdx.x, ty = threadIdx.y;
    const float* src = thetas + (size_t)l * Hh * Hh;
#pragma unroll
    for (int j = 0; j < 4; j++)
        t[ty + j*8][tx] = src[(size_t)(y0 + ty + j*8)*Hh + x0 + tx];
    __syncthreads();
#pragma unroll
    for (int j = 0; j < 4; j++)
        g_thT[(size_t)l*Hh*Hh + (size_t)(x0 + ty + j*8)*Hh + y0 + tx] = t[tx][ty + j*8];
}

// ---------------- BN finalize: stats -> per-(b,h) scale/shift ----------------
__global__ void k_bnfin(const float* __restrict__ gam,
                        const float* __restrict__ bet, int l) {
    int i = blockIdx.x * 256 + threadIdx.x;
    int h = i & (Hh - 1);
    float mean = g_sum[i] * (1.f / Nn);
    float var  = g_sq [i] * (1.f / Nn) - mean * mean;
    float sc = rsqrtf(var + EPSf) * gam[l*Hh + h];
    g_bnA[i] = sc;
    g_bnB[i] = bet[l*Hh + h] - mean * sc;
}

// ---------------- last-layer: hs = h + relu(BN(hcT)) row-major ----------------
__global__ void k_bn_last() {
    __shared__ float t[32][33];
    int b  = blockIdx.z;
    int h0 = blockIdx.x * 32, n0 = blockIdx.y * 32;
    int tx = threadIdx.x, ty = threadIdx.y;
#pragma unroll
    for (int j = 0; j < 4; j++) {
        int h = h0 + ty + j*8;
        float v = g_hcT[((size_t)b*Hh + h)*Nn + n0 + tx];
        t[ty + j*8][tx] = fmaxf(fmaf(v, g_bnA[b*Hh + h], g_bnB[b*Hh + h]), 0.f);
    }
    __syncthreads();
#pragma unroll
    for (int j = 0; j < 4; j++) {
        size_t ix = ((size_t)b*Nn + n0 + ty + j*8)*Hh + h0 + tx;
        g_hs[ix] = g_h[ix] + t[tx][ty + j*8];
    }
}

// ---------------- decoder: out = hs @ Wdec + bdec ----------------
__global__ void k_decoder(const float* __restrict__ Wdec,
                          const float* __restrict__ bdec,
                          float* __restrict__ out) {
    __shared__ float Ws[Hh*Pout + 32];
    int tid = threadIdx.x;
    for (int i = tid; i < Hh*Pout; i += 256) Ws[i] = Wdec[i];
    __syncthreads();
    int row  = blockIdx.x * 8 + (tid >> 5);
    int lane = tid & 31;
    const float* xs = g_hs + (size_t)row * Hh;
    float xr[8];
#pragma unroll
    for (int j = 0; j < 8; j++) xr[j] = xs[lane + j*32];
    float acc = 0.f;
    int wl = (lane < Pout) ? lane : 0;
#pragma unroll 4
    for (int k = 0; k < Hh; k++) {
        float xv = __shfl_sync(0xffffffffu, xr[k >> 5], k & 31);
        acc = fmaf(xv, Ws[k*Pout + wl], acc);
    }
    if (lane < Pout)
        out[(size_t)row*Pout + lane] = acc + bdec[lane];
}

// ---------------- launch ----------------
extern "C" void kernel_launch(void* const* d_in, const int* in_sizes, int n_in,
                              void* d_out, int out_size) {
    const float* obs    = (const float*)d_in[0];
    const int*   idx    = (const int*)  d_in[1];
    const float* Wenc   = (const float*)d_in[2];
    const float* benc   = (const float*)d_in[3];
    const float* thetas = (const float*)d_in[4];
    const float* cbias  = (const float*)d_in[5];
    const float* gam    = (const float*)d_in[6];
    const float* bet    = (const float*)d_in[7];
    const float* Wdec   = (const float*)d_in[8];
    const float* bdec   = (const float*)d_in[9];
    float* out = (float*)d_out;

    float *dHc, *dHcT, *dhsT, *dhcT, *dYp, *dZT, *dthT, *dinvb, *dinvd, *dbnA, *dbnB;
    cudaGetSymbolAddress((void**)&dHc,   g_Hc);
    cudaGetSymbolAddress((void**)&dHcT,  g_HcT);
    cudaGetSymbolAddress((void**)&dhsT,  g_hsT);
    cudaGetSymbolAddress((void**)&dhcT,  g_hcT);
    cudaGetSymbolAddress((void**)&dYp,   g_Yp);
    cudaGetSymbolAddress((void**)&dZT,   g_ZT);
    cudaGetSymbolAddress((void**)&dthT,  g_thT);
    cudaGetSymbolAddress((void**)&dinvb, g_invb);
    cudaGetSymbolAddress((void**)&dinvd, g_invd);
    cudaGetSymbolAddress((void**)&dbnA,  g_bnA);
    cudaGetSymbolAddress((void**)&dbnB,  g_bnB);

    const int SMEM_G = (2*AFL + 2*BFL) * 4;   // 48KB
    const int SMEM_C = (2*AFL + 4*BFL) * 4;   // 64KB (COMBINE)
    const int SMEM_B = 65536;                  // k_build2 packed counts
    cudaFuncSetAttribute((const void*)k_mma2<0,0,0,0,0,0,0>, cudaFuncAttributeMaxDynamicSharedMemorySize, SMEM_G);
    cudaFuncSetAttribute((const void*)k_mma2<0,0,1,0,0,0,0>, cudaFuncAttributeMaxDynamicSharedMemorySize, SMEM_G);
    cudaFuncSetAttribute((const void*)k_mma2<1,1,0,0,0,0,0>, cudaFuncAttributeMaxDynamicSharedMemorySize, SMEM_C);
    cudaFuncSetAttribute((const void*)k_mma2<0,0,0,1,1,1,1>, cudaFuncAttributeMaxDynamicSharedMemorySize, SMEM_G);
    cudaFuncSetAttribute((const void*)k_build2, cudaFuncAttributeMaxDynamicSharedMemorySize, SMEM_B);

    k_encoder<<<Bn*Nn, Hh>>>(obs, Wenc, benc);
    k_build2<<<Bn, 256, SMEM_B>>>(idx);
    k_trans_theta<<<dim3(Hh/32, Hh/32, Ll), dim3(32, 8)>>>(thetas);

    for (int l = 0; l < Ll; l++) {
        // S1 split-K (zeroes BN stats): Yp[y] = HcT @ Bsrc^T over K-slice y
        if (l == 0) {
            k_mma2<0,0,0,0,0,0,0><<<dim3(4, 2, Bn), 256, SMEM_G>>>(dHcT, dhsT, dYp,
                nullptr, nullptr, nullptr, 0L, nullptr, nullptr,
                256, Nn, Nn, Hh, Mm,
                (long)Mm*Nn, (long)Hh*Nn, (long)Mm*Hh, 1, 256, (long)Bn*Mm*Hh);
        } else {
            k_mma2<0,0,1,0,0,0,0><<<dim3(4, 2, Bn), 256, SMEM_G>>>(dHcT, dhcT, dYp,
                nullptr, nullptr, nullptr, 0L, dbnA, dbnB,
                256, Nn, Nn, Hh, Mm,
                (long)Mm*Nn, (long)Hh*Nn, (long)Mm*Hh, 1, 256, (long)Bn*Mm*Hh);
        }
        // S2: ZT[b](256x128) = thT_l @ [invb*(Yp0+Yp1)]^T
        k_mma2<1,1,0,0,0,0,0><<<dim3(2, 2, Bn), 256, SMEM_C>>>(dthT + (size_t)l*Hh*Hh, dYp, dZT,
            nullptr, nullptr, dinvb, (long)Bn*Mm*Hh, nullptr, nullptr,
            256, Hh, Hh, Mm, Hh,
            0L, (long)Mm*Hh, (long)Hh*Mm, 0, 0, 0L);
        // S3: hcT = (Dinv*(Hc @ ZT^T) + bias)^T, fused BN stats, transposed write
        k_mma2<0,0,0,1,1,1,1><<<dim3(4, 4, Bn), 256, SMEM_G>>>(dHc, dZT, dhcT,
            dinvd, cbias + (size_t)l*Hh, nullptr, 0L, nullptr, nullptr,
            128, Mm, Mm, Nn, Nn,
            (long)Nn*Mm, (long)Hh*Mm, (long)Hh*Nn, 0, 0, 0L);
        k_bnfin<<<Bn*Hh/256, 256>>>(gam, bet, l);
    }

    k_bn_last<<<dim3(Hh/32, Nn/32, Bn), dim3(32, 8)>>>();
    k_decoder<<<Bn*Nn/8, 256>>>(Wdec, bdec, out);
}

// round 16
// speedup vs baseline: 1.0387x; 1.0387x over previous
#include <cuda_runtime.h>
#include <cstdint>

#define Bn   64
#define Nn   512
#define Tt   8
#define DINd 2
#define Hh   256
#define Ll   3
#define Ee   8192
#define Mm   128
#define Pout 24
#define EPSf 1e-5f

// ---------------- scratch (allocation-free) ----------------
__device__ float g_h    [Bn*Nn*Hh];
__device__ float g_hs   [Bn*Nn*Hh];    // h + relu(BN(hc)) row-major (decoder input)
__device__ float g_hsT  [Bn*Hh*Nn];    // encoder output^T (layer-0 S1 B operand)
__device__ float g_hcT  [Bn*Hh*Nn];    // conv output^T pre-BN (written by S3)
__device__ float g_Yp   [2*Bn*Mm*Hh];  // S1 split-K partials (consumed by S2)
__device__ float g_ZT   [Bn*Hh*Mm];    // (Y @ theta)^T, fp32
__device__ float g_Hc   [Bn*Nn*Mm];    // raw integer counts (tf32-exact)
__device__ float g_HcT  [Bn*Mm*Nn];    // raw integer counts (tf32-exact)
__device__ float g_thT  [Ll*Hh*Hh];    // theta^T, fp32
__device__ float g_invb [Bn*Mm];
__device__ float g_invd [Bn*Nn];
__device__ int   g_cntm [Bn*Mm];
__device__ int   g_cntn [Bn*Nn];
__device__ float g_sum  [2*Bn*Hh];     // BN stats, double-buffered by layer parity
__device__ float g_sq   [2*Bn*Hh];

// ================= helpers =================
__device__ __forceinline__ uint32_t smem_u32(const void* p) {
    uint32_t a;
    asm("{ .reg .u64 t; cvta.to.shared.u64 t, %1; cvt.u32.u64 %0, t; }" : "=r"(a) : "l"(p));
    return a;
}
__device__ __forceinline__ uint32_t lo_tf32(uint32_t vbits) {
    float hi = __uint_as_float(vbits & 0xffffe000u);
    return __float_as_uint(__uint_as_float(vbits) - hi);
}
__device__ __forceinline__ void bn_params(float s, float q, float gm, float bt,
                                          float& sc, float& sh) {
    float mean = s * (1.f / Nn);
    float var  = q * (1.f / Nn) - mean * mean;
    sc = rsqrtf(var + EPSf) * gm;
    sh = bt - mean * sc;
}
#define CP16(dst, src) asm volatile("cp.async.cg.shared.global [%0], [%1], 16;" :: "r"(dst), "l"(src) : "memory")
#define CPCOMMIT()     asm volatile("cp.async.commit_group;" ::: "memory")
#define CPWAIT1()      asm volatile("cp.async.wait_group 1;" ::: "memory")

__device__ __forceinline__ void ldsm4(uint32_t* r, uint32_t addr) {
    asm volatile("ldmatrix.sync.aligned.m8n8.x4.shared.b16 {%0,%1,%2,%3}, [%4];"
        : "=r"(r[0]), "=r"(r[1]), "=r"(r[2]), "=r"(r[3]) : "r"(addr));
}
__device__ __forceinline__ void mma_tf32(float* c, const uint32_t* a, const uint32_t* b) {
    asm volatile(
        "mma.sync.aligned.m16n8k8.row.col.f32.tf32.tf32.f32 "
        "{%0,%1,%2,%3}, {%4,%5,%6,%7}, {%8,%9}, {%0,%1,%2,%3};"
        : "+f"(c[0]), "+f"(c[1]), "+f"(c[2]), "+f"(c[3])
        : "r"(a[0]), "r"(a[1]), "r"(a[2]), "r"(a[3]), "r"(b[0]), "r"(b[1]));
}

// ================= error-compensated tf32 mma.sync GEMM =================
// Block 128x64 (MxN), BK=32, 8 warps (2m x 4n), warp tile 64x16; ldmatrix loads.
// hi operand = raw fp32 bits (HW truncates), lo = exact truncation residual.
// SPLITA: add A-lo term. COMBINE: B := (B + B[bOff2]) * rowscaleB[row].
// BNB: B := relu(B*sc+sh), sc/sh computed inline from prev-layer stats+gamma/beta.
// TRANSC: smem-staged transposed C. STATS/RS/BIAS: epilogue features.
// statoff selects the stats parity buffer for zstats/STATS.
#define AFL 4096
#define BFL 2048
#define O_B  8192
#define O_B2 12288

template<int SPLITA, int COMBINE, int BNB, int TRANSC, int STATS, int RS, int BIAS>
__global__ void __launch_bounds__(256, 3)
k_mma2(const float* __restrict__ Ag, const float* __restrict__ Bg,
       float* __restrict__ Cg,
       const float* __restrict__ rowscale, const float* __restrict__ bias,
       const float* __restrict__ rowscaleB, long bOff2,
       const float* __restrict__ pSum, const float* __restrict__ pSq,
       const float* __restrict__ pGam, const float* __restrict__ pBet,
       int statoff,
       int K, int lda, int ldb, int N, int M,
       long sA, long sB, long sC, int zstats,
       int koffY, long cOffY) {
    extern __shared__ float sm[];
    uint32_t sbase = smem_u32(sm);

    int tid = threadIdx.x, lane = tid & 31, wid = tid >> 5;
    int wm = wid >> 2, wn = wid & 3;           // 2 x 4 warp grid, warp tile 64x16
    int col0 = blockIdx.x * 64;
    int row0, k_base;
    long cadd;
    if (koffY) { row0 = 0; k_base = blockIdx.y * koffY; cadd = (long)blockIdx.y * cOffY; }
    else       { row0 = blockIdx.y * 128; k_base = 0; cadd = 0; }
    int z = blockIdx.z;

    if (zstats && blockIdx.y == 0 && tid < 64) {
        g_sum[statoff + z * Hh + col0 + tid] = 0.f;
        g_sq [statoff + z * Hh + col0 + tid] = 0.f;
    }

    const float* A  = Ag + (size_t)z * sA + k_base;
    const float* B  = Bg + (size_t)z * sB + k_base;
    const float* B2 = COMBINE ? (Bg + bOff2 + (size_t)z * sB + k_base) : nullptr;
    float* C = Cg + (size_t)z * sC + cadd;

    int cr = tid >> 3;                 // 0..31
    int cc = (tid & 7) * 4;

    float acc[4][2][4];
#pragma unroll
    for (int i = 0; i < 4; i++)
#pragma unroll
        for (int j = 0; j < 2; j++)
#pragma unroll
            for (int q = 0; q < 4; q++) acc[i][j][q] = 0.f;

    int nkb = K >> 5;
    int g = lane >> 2, t = lane & 3;

    float rsB[2], bAc[2], bBc[2];
    if (COMBINE) {
#pragma unroll
        for (int nf = 0; nf < 2; nf++)
            rsB[nf] = rowscaleB[(size_t)z * Mm + col0 + wn * 16 + nf * 8 + g];
    }
    if (BNB) {
#pragma unroll
        for (int nf = 0; nf < 2; nf++) {
            int h = col0 + wn * 16 + nf * 8 + g;
            bn_params(pSum[z*Hh + h], pSq[z*Hh + h], pGam[h], pBet[h], bAc[nf], bBc[nf]);
        }
    }

    // ldmatrix per-lane addressing
    int lrow = lane & 7;
    int lsub = lane >> 3;
    uint32_t rm4  = (uint32_t)lrow << 4;
    uint32_t cb4A = (uint32_t)(lsub >> 1) << 4;
    uint32_t cb4B = (uint32_t)(lsub & 1) << 4;
    uint32_t aAddr[4], bAddr;
#pragma unroll
    for (int mf = 0; mf < 4; mf++)
        aAddr[mf] = sbase + (uint32_t)((wm * 64 + mf * 16 + ((lsub & 1) << 3) + lrow) << 7);
    bAddr = sbase + O_B * 4 + (uint32_t)((wn * 16 + (lsub >> 1) * 8 + lrow) << 7);

#pragma unroll
    for (int s = 0; s < 2; s++) {
        int kk = s * 32;
#pragma unroll
        for (int i = 0; i < 4; i++) {             // A: 128 rows, 256 threads
            int rr = cr + i * 32;
            uint32_t so = (uint32_t)(s * AFL + rr * 32 + (cc ^ ((rr & 7) * 4))) * 4;
            CP16(sbase + so, A + (size_t)(row0 + rr) * lda + kk + cc);
        }
#pragma unroll
        for (int i = 0; i < 2; i++) {             // B: 64 rows
            int rr = cr + i * 32;
            uint32_t sw = (uint32_t)(rr * 32 + (cc ^ ((rr & 7) * 4)));
            size_t gb = (size_t)(col0 + rr) * ldb + kk + cc;
            CP16(sbase + (uint32_t)(O_B + s * BFL + sw) * 4, B + gb);
            if (COMBINE) CP16(sbase + (uint32_t)(O_B2 + s * BFL + sw) * 4, B2 + gb);
        }
        CPCOMMIT();
    }

    for (int kb = 0; kb < nkb; kb++) {
        int s = kb & 1;
        CPWAIT1();
        __syncthreads();
        uint32_t aOffS = (uint32_t)(s * AFL) * 4;
        uint32_t bOffS = (uint32_t)(s * BFL) * 4;

#pragma unroll
        for (int ks = 0; ks < 4; ks++) {
            uint32_t ka  = (((uint32_t)ks << 5) + cb4A) ^ rm4;
            uint32_t kbo = (((uint32_t)ks << 5) + cb4B) ^ rm4;
            uint32_t a[4][4], bR[2][2], bl[2][2];
#pragma unroll
            for (int mf = 0; mf < 4; mf++)
                ldsm4(a[mf], aAddr[mf] + aOffS + ka);
            {
                uint32_t r[4];
                ldsm4(r, bAddr + bOffS + kbo);
                bR[0][0] = r[0]; bR[0][1] = r[1]; bR[1][0] = r[2]; bR[1][1] = r[3];
            }
            if (COMBINE) {
                uint32_t r[4];
                ldsm4(r, bAddr + (O_B2 - O_B) * 4 + bOffS + kbo);
#pragma unroll
                for (int nf = 0; nf < 2; nf++)
#pragma unroll
                    for (int q = 0; q < 2; q++) {
                        float u = (__uint_as_float(bR[nf][q]) + __uint_as_float(r[nf*2+q])) * rsB[nf];
                        bR[nf][q] = __float_as_uint(u);
                    }
            }
            if (BNB) {
#pragma unroll
                for (int nf = 0; nf < 2; nf++)
#pragma unroll
                    for (int q = 0; q < 2; q++) {
                        float u = fmaxf(fmaf(__uint_as_float(bR[nf][q]), bAc[nf], bBc[nf]), 0.f);
                        bR[nf][q] = __float_as_uint(u);
                    }
            }
#pragma unroll
            for (int nf = 0; nf < 2; nf++) {
                bl[nf][0] = lo_tf32(bR[nf][0]);
                bl[nf][1] = lo_tf32(bR[nf][1]);
            }
#pragma unroll
            for (int mf = 0; mf < 4; mf++)
#pragma unroll
                for (int nf = 0; nf < 2; nf++)
                    mma_tf32(acc[mf][nf], a[mf], bR[nf]);
#pragma unroll
            for (int mf = 0; mf < 4; mf++)
#pragma unroll
                for (int nf = 0; nf < 2; nf++)
                    mma_tf32(acc[mf][nf], a[mf], bl[nf]);
            if (SPLITA) {
                uint32_t al[4][4];
#pragma unroll
                for (int mf = 0; mf < 4; mf++)
#pragma unroll
                    for (int q = 0; q < 4; q++)
                        al[mf][q] = lo_tf32(a[mf][q]);
#pragma unroll
                for (int mf = 0; mf < 4; mf++)
#pragma unroll
                    for (int nf = 0; nf < 2; nf++)
                        mma_tf32(acc[mf][nf], al[mf], bR[nf]);
            }
        }
        __syncthreads();

        if (kb + 2 < nkb) {
            int kk = (kb + 2) * 32;
#pragma unroll
            for (int i = 0; i < 4; i++) {
                int rr = cr + i * 32;
                uint32_t so = (uint32_t)(s * AFL + rr * 32 + (cc ^ ((rr & 7) * 4))) * 4;
                CP16(sbase + so, A + (size_t)(row0 + rr) * lda + kk + cc);
            }
#pragma unroll
            for (int i = 0; i < 2; i++) {
                int rr = cr + i * 32;
                uint32_t sw = (uint32_t)(rr * 32 + (cc ^ ((rr & 7) * 4)));
                size_t gb = (size_t)(col0 + rr) * ldb + kk + cc;
                CP16(sbase + (uint32_t)(O_B + s * BFL + sw) * 4, B + gb);
                if (COMBINE) CP16(sbase + (uint32_t)(O_B2 + s * BFL + sw) * 4, B2 + gb);
            }
        }
        CPCOMMIT();
    }

    // ---------------- epilogue ----------------
    const float* rsb = RS ? (rowscale + (size_t)z * M) : nullptr;
    float cs[STATS ? 4 : 1], cq[STATS ? 4 : 1];
    if (STATS) {
#pragma unroll
        for (int i = 0; i < 4; i++) { cs[i] = 0.f; cq[i] = 0.f; }
    }
    if (TRANSC) __syncthreads();

#pragma unroll
    for (int mf = 0; mf < 4; mf++) {
        int rl = wm * 64 + mf * 16 + g;
        int rr = row0 + rl;
        float rs0 = RS ? rsb[rr]     : 1.f;
        float rs1 = RS ? rsb[rr + 8] : 1.f;
#pragma unroll
        for (int nf = 0; nf < 2; nf++) {
            int cl  = wn * 16 + nf * 8 + t * 2;
            int ccg = col0 + cl;
            float c0 = acc[mf][nf][0] * rs0, c1 = acc[mf][nf][1] * rs0;
            float c2 = acc[mf][nf][2] * rs1, c3 = acc[mf][nf][3] * rs1;
            if (BIAS) {
                float b0 = bias[ccg], b1 = bias[ccg + 1];
                c0 += b0; c1 += b1; c2 += b0; c3 += b1;
            }
            if (STATS) {
                cs[nf*2]   += c0 + c2;  cs[nf*2+1] += c1 + c3;
                cq[nf*2]   += c0*c0 + c2*c2;
                cq[nf*2+1] += c1*c1 + c3*c3;
            }
            if (TRANSC) {
                sm[cl       * 132 + rl    ] = c0;
                sm[(cl + 1) * 132 + rl    ] = c1;
                sm[cl       * 132 + rl + 8] = c2;
                sm[(cl + 1) * 132 + rl + 8] = c3;
            } else {
                *reinterpret_cast<float2*>(&C[(size_t)rr * N + ccg])       = make_float2(c0, c1);
                *reinterpret_cast<float2*>(&C[(size_t)(rr + 8) * N + ccg]) = make_float2(c2, c3);
            }
        }
    }
    if (TRANSC) {
        __syncthreads();
        for (int i = tid; i < 64 * 32; i += 256) {
            int h  = i >> 5;
            int n4 = (i & 31) << 2;
            float4 v = *reinterpret_cast<float4*>(&sm[h * 132 + n4]);
            *reinterpret_cast<float4*>(&C[(size_t)(col0 + h) * N + row0 + n4]) = v;
        }
    }
    if (STATS) {
#pragma unroll
        for (int off = 4; off <= 16; off <<= 1) {
#pragma unroll
            for (int i = 0; i < 4; i++) {
                cs[i] += __shfl_xor_sync(0xffffffffu, cs[i], off);
                cq[i] += __shfl_xor_sync(0xffffffffu, cq[i], off);
            }
        }
        if (g == 0) {
#pragma unroll
            for (int nf = 0; nf < 2; nf++) {
#pragma unroll
                for (int j = 0; j < 2; j++) {
                    int ccg = col0 + wn * 16 + nf * 8 + t * 2 + j;
                    atomicAdd(&g_sum[statoff + z * Hh + ccg], cs[nf*2+j]);
                    atomicAdd(&g_sq [statoff + z * Hh + ccg], cq[nf*2+j]);
                }
            }
        }
    }
}

// ---------------- encoder ----------------
__global__ void k_encoder(const float* __restrict__ obs,
                          const float* __restrict__ Wenc,
                          const float* __restrict__ benc) {
    int bn = blockIdx.x;
    int h  = threadIdx.x;
    int b  = bn >> 9, n = bn & (Nn - 1);
    __shared__ float srow[Tt*DINd];
    if (h < Tt*DINd) srow[h] = obs[bn*Tt*DINd + h];
    __syncthreads();
    float w0 = Wenc[h], w1 = Wenc[Hh + h], bb = benc[h];
    float acc = 0.f;
#pragma unroll
    for (int t = 0; t < Tt; t++) {
        float v = fmaf(srow[2*t], w0, fmaf(srow[2*t+1], w1, bb));
        acc += fmaxf(v, 0.f);
    }
    float r = acc * (1.f / Tt);
    g_h[(size_t)bn*Hh + h] = r;
    g_hsT[((size_t)b*Hh + h)*Nn + n] = r;
}

// ---------------- incidence build (raw counts) ----------------
__global__ void k_zero_dense() {
    int i = blockIdx.x * blockDim.x + threadIdx.x;
    g_Hc[i]  = 0.f;
    g_HcT[i] = 0.f;
    if (i < Bn*Mm) g_cntm[i] = 0;
    if (i < Bn*Nn) g_cntn[i] = 0;
}
__global__ void k_build(const int* __restrict__ idx) {
    int i = blockIdx.x * blockDim.x + threadIdx.x;
    int b = i >> 13, e = i & (Ee - 1);
    int n = idx[b*2*Ee + e];
    int m = idx[b*2*Ee + Ee + e];
    atomicAdd(&g_Hc [((size_t)b*Nn + n)*Mm + m], 1.f);
    atomicAdd(&g_HcT[((size_t)b*Mm + m)*Nn + n], 1.f);
    atomicAdd(&g_cntn[b*Nn + n], 1);
    atomicAdd(&g_cntm[b*Mm + m], 1);
}
__global__ void k_invdeg() {
    int i = blockIdx.x * blockDim.x + threadIdx.x;
    if (i < Bn*Mm) g_invb[i] = 1.f / fmaxf((float)g_cntm[i], 1.f);
    if (i < Bn*Nn) g_invd[i] = 1.f / fmaxf((float)g_cntn[i], 1.f);
}

// ---------------- theta transpose ----------------
__global__ void k_trans_theta(const float* __restrict__ thetas) {
    __shared__ float t[32][33];
    int l  = blockIdx.z;
    int x0 = blockIdx.x * 32, y0 = blockIdx.y * 32;
    int tx = threadIdx.x, ty = threadIdx.y;
    const float* src = thetas + (size_t)l * Hh * Hh;
#pragma unroll
    for (int j = 0; j < 4; j++)
        t[ty + j*8][tx] = src[(size_t)(y0 + ty + j*8)*Hh + x0 + tx];
    __syncthreads();
#pragma unroll
    for (int j = 0; j < 4; j++)
        g_thT[(size_t)l*Hh*Hh + (size_t)(x0 + ty + j*8)*Hh + y0 + tx] = t[tx][ty + j*8];
}

// ---------------- last-layer: hs = h + relu(BN(hcT)) row-major ----------------
__global__ void k_bn_last(const float* __restrict__ gam,
                          const float* __restrict__ bet, int statoff) {
    __shared__ float t[32][33];
    int b  = blockIdx.z;
    int h0 = blockIdx.x * 32, n0 = blockIdx.y * 32;
    int tx = threadIdx.x, ty = threadIdx.y;
#pragma unroll
    for (int j = 0; j < 4; j++) {
        int h = h0 + ty + j*8;
        float sc, sh;
        bn_params(g_sum[statoff + b*Hh + h], g_sq[statoff + b*Hh + h], gam[h], bet[h], sc, sh);
        float v = g_hcT[((size_t)b*Hh + h)*Nn + n0 + tx];
        t[ty + j*8][tx] = fmaxf(fmaf(v, sc, sh), 0.f);
    }
    __syncthreads();
#pragma unroll
    for (int j = 0; j < 4; j++) {
        size_t ix = ((size_t)b*Nn + n0 + ty + j*8)*Hh + h0 + tx;
        g_hs[ix] = g_h[ix] + t[tx][ty + j*8];
    }
}

// ---------------- decoder: out = hs @ Wdec + bdec ----------------
__global__ void k_decoder(const float* __restrict__ Wdec,
                          const float* __restrict__ bdec,
                          float* __restrict__ out) {
    __shared__ float Ws[Hh*Pout + 32];
    int tid = threadIdx.x;
    for (int i = tid; i < Hh*Pout; i += 256) Ws[i] = Wdec[i];
    __syncthreads();
    int row  = blockIdx.x * 8 + (tid >> 5);
    int lane = tid & 31;
    const float* xs = g_hs + (size_t)row * Hh;
    float xr[8];
#pragma unroll
    for (int j = 0; j < 8; j++) xr[j] = xs[lane + j*32];
    float acc = 0.f;
    int wl = (lane < Pout) ? lane : 0;
#pragma unroll 4
    for (int k = 0; k < Hh; k++) {
        float xv = __shfl_sync(0xffffffffu, xr[k >> 5], k & 31);
        acc = fmaf(xv, Ws[k*Pout + wl], acc);
    }
    if (lane < Pout)
        out[(size_t)row*Pout + lane] = acc + bdec[lane];
}

// ---------------- launch ----------------
extern "C" void kernel_launch(void* const* d_in, const int* in_sizes, int n_in,
                              void* d_out, int out_size) {
    const float* obs    = (const float*)d_in[0];
    const int*   idx    = (const int*)  d_in[1];
    const float* Wenc   = (const float*)d_in[2];
    const float* benc   = (const float*)d_in[3];
    const float* thetas = (const float*)d_in[4];
    const float* cbias  = (const float*)d_in[5];
    const float* gam    = (const float*)d_in[6];
    const float* bet    = (const float*)d_in[7];
    const float* Wdec   = (const float*)d_in[8];
    const float* bdec   = (const float*)d_in[9];
    float* out = (float*)d_out;

    float *dHc, *dHcT, *dhsT, *dhcT, *dYp, *dZT, *dthT, *dinvb, *dinvd, *dsum, *dsq;
    cudaGetSymbolAddress((void**)&dHc,   g_Hc);
    cudaGetSymbolAddress((void**)&dHcT,  g_HcT);
    cudaGetSymbolAddress((void**)&dhsT,  g_hsT);
    cudaGetSymbolAddress((void**)&dhcT,  g_hcT);
    cudaGetSymbolAddress((void**)&dYp,   g_Yp);
    cudaGetSymbolAddress((void**)&dZT,   g_ZT);
    cudaGetSymbolAddress((void**)&dthT,  g_thT);
    cudaGetSymbolAddress((void**)&dinvb, g_invb);
    cudaGetSymbolAddress((void**)&dinvd, g_invd);
    cudaGetSymbolAddress((void**)&dsum,  g_sum);
    cudaGetSymbolAddress((void**)&dsq,   g_sq);

    const int SMEM_G = (2*AFL + 2*BFL) * 4;   // 48KB
    const int SMEM_C = (2*AFL + 4*BFL) * 4;   // 64KB (COMBINE)
    cudaFuncSetAttribute((const void*)k_mma2<0,0,0,0,0,0,0>, cudaFuncAttributeMaxDynamicSharedMemorySize, SMEM_G);
    cudaFuncSetAttribute((const void*)k_mma2<0,0,1,0,0,0,0>, cudaFuncAttributeMaxDynamicSharedMemorySize, SMEM_G);
    cudaFuncSetAttribute((const void*)k_mma2<1,1,0,0,0,0,0>, cudaFuncAttributeMaxDynamicSharedMemorySize, SMEM_C);
    cudaFuncSetAttribute((const void*)k_mma2<0,0,0,1,1,1,1>, cudaFuncAttributeMaxDynamicSharedMemorySize, SMEM_G);

    k_encoder<<<Bn*Nn, Hh>>>(obs, Wenc, benc);
    k_zero_dense<<<Bn*Nn*Mm/256, 256>>>();
    k_build<<<Bn*Ee/256, 256>>>(idx);

    for (int l = 0; l < Ll; l++) {
        int soff  = (l & 1) * Bn * Hh;
        int spoff = ((l - 1) & 1) * Bn * Hh;
        // S1 split-K (zeroes this layer's stats): Yp[y] = HcT @ Bsrc^T over K-slice y
        if (l == 0) {
            k_mma2<0,0,0,0,0,0,0><<<dim3(4, 2, Bn), 256, SMEM_G>>>(dHcT, dhsT, dYp,
                nullptr, nullptr, nullptr, 0L,
                nullptr, nullptr, nullptr, nullptr, soff,
                256, Nn, Nn, Hh, Mm,
                (long)Mm*Nn, (long)Hh*Nn, (long)Mm*Hh, 1, 256, (long)Bn*Mm*Hh);
            k_invdeg<<<(Bn*Nn + 255)/256, 256>>>();
            k_trans_theta<<<dim3(Hh/32, Hh/32, Ll), dim3(32, 8)>>>(thetas);
        } else {
            k_mma2<0,0,1,0,0,0,0><<<dim3(4, 2, Bn), 256, SMEM_G>>>(dHcT, dhcT, dYp,
                nullptr, nullptr, nullptr, 0L,
                dsum + spoff, dsq + spoff, gam + (size_t)(l-1)*Hh, bet + (size_t)(l-1)*Hh, soff,
                256, Nn, Nn, Hh, Mm,
                (long)Mm*Nn, (long)Hh*Nn, (long)Mm*Hh, 1, 256, (long)Bn*Mm*Hh);
        }
        // S2: ZT[b](256x128) = thT_l @ [invb*(Yp0+Yp1)]^T
        k_mma2<1,1,0,0,0,0,0><<<dim3(2, 2, Bn), 256, SMEM_C>>>(dthT + (size_t)l*Hh*Hh, dYp, dZT,
            nullptr, nullptr, dinvb, (long)Bn*Mm*Hh,
            nullptr, nullptr, nullptr, nullptr, 0,
            256, Hh, Hh, Mm, Hh,
            0L, (long)Mm*Hh, (long)Hh*Mm, 0, 0, 0L);
        // S3: hcT = (Dinv*(Hc @ ZT^T) + bias)^T, fused BN stats, transposed write
        k_mma2<0,0,0,1,1,1,1><<<dim3(4, 4, Bn), 256, SMEM_G>>>(dHc, dZT, dhcT,
            dinvd, cbias + (size_t)l*Hh, nullptr, 0L,
            nullptr, nullptr, nullptr, nullptr, soff,
            128, Mm, Mm, Nn, Nn,
            (long)Nn*Mm, (long)Hh*Mm, (long)Hh*Nn, 0, 0, 0L);
    }

    k_bn_last<<<dim3(Hh/32, Nn/32, Bn), dim3(32, 8)>>>(
        gam + (size_t)(Ll-1)*Hh, bet + (size_t)(Ll-1)*Hh, ((Ll-1) & 1) * Bn * Hh);
    k_decoder<<<Bn*Nn/8, 256>>>(Wdec, bdec, out);
}

// round 17
// speedup vs baseline: 1.0702x; 1.0304x over previous
#include <cuda_runtime.h>
#include <cstdint>

#define Bn   64
#define Nn   512
#define Tt   8
#define DINd 2
#define Hh   256
#define Ll   3
#define Ee   8192
#define Mm   128
#define Pout 24
#define EPSf 1e-5f

// ---------------- scratch (allocation-free) ----------------
__device__ float g_h    [Bn*Nn*Hh];
__device__ float g_hsT  [Bn*Hh*Nn];    // encoder output^T (layer-0 S1 B operand)
__device__ float g_hcT  [Bn*Hh*Nn];    // conv output^T pre-BN (written by S3)
__device__ float g_Yp   [2*Bn*Mm*Hh];  // S1 split-K partials (consumed by S2)
__device__ float g_ZT   [Bn*Hh*Mm];    // (Y @ theta)^T, fp32
__device__ float g_Hc   [Bn*Nn*Mm];    // raw integer counts (tf32-exact)
__device__ float g_HcT  [Bn*Mm*Nn];    // raw integer counts (tf32-exact)
__device__ float g_thT  [Ll*Hh*Hh];    // theta^T, fp32
__device__ float g_invb [Bn*Mm];
__device__ float g_invd [Bn*Nn];
__device__ int   g_cntm [Bn*Mm];
__device__ int   g_cntn [Bn*Nn];
__device__ float g_sum  [2*Bn*Hh];     // BN stats, double-buffered by layer parity
__device__ float g_sq   [2*Bn*Hh];

// ================= helpers =================
__device__ __forceinline__ uint32_t smem_u32(const void* p) {
    uint32_t a;
    asm("{ .reg .u64 t; cvta.to.shared.u64 t, %1; cvt.u32.u64 %0, t; }" : "=r"(a) : "l"(p));
    return a;
}
__device__ __forceinline__ uint32_t lo_tf32(uint32_t vbits) {
    float hi = __uint_as_float(vbits & 0xffffe000u);
    return __float_as_uint(__uint_as_float(vbits) - hi);
}
__device__ __forceinline__ void bn_params(float s, float q, float gm, float bt,
                                          float& sc, float& sh) {
    float mean = s * (1.f / Nn);
    float var  = q * (1.f / Nn) - mean * mean;
    sc = rsqrtf(var + EPSf) * gm;
    sh = bt - mean * sc;
}
#define CP16(dst, src) asm volatile("cp.async.cg.shared.global [%0], [%1], 16;" :: "r"(dst), "l"(src) : "memory")
#define CPCOMMIT()     asm volatile("cp.async.commit_group;" ::: "memory")
#define CPWAIT1()      asm volatile("cp.async.wait_group 1;" ::: "memory")

__device__ __forceinline__ void ldsm4(uint32_t* r, uint32_t addr) {
    asm volatile("ldmatrix.sync.aligned.m8n8.x4.shared.b16 {%0,%1,%2,%3}, [%4];"
        : "=r"(r[0]), "=r"(r[1]), "=r"(r[2]), "=r"(r[3]) : "r"(addr));
}
__device__ __forceinline__ void mma_tf32(float* c, const uint32_t* a, const uint32_t* b) {
    asm volatile(
        "mma.sync.aligned.m16n8k8.row.col.f32.tf32.tf32.f32 "
        "{%0,%1,%2,%3}, {%4,%5,%6,%7}, {%8,%9}, {%0,%1,%2,%3};"
        : "+f"(c[0]), "+f"(c[1]), "+f"(c[2]), "+f"(c[3])
        : "r"(a[0]), "r"(a[1]), "r"(a[2]), "r"(a[3]), "r"(b[0]), "r"(b[1]));
}

// ================= error-compensated tf32 mma.sync GEMM =================
// Block 128x64 (MxN), BK=32, 8 warps (2m x 4n), warp tile 64x16; ldmatrix loads.
// hi operand = raw fp32 bits (HW truncates), lo = exact truncation residual.
// SPLITA: add A-lo term. COMBINE: B := (B + B[bOff2]) * rowscaleB[row].
// BNB: B := relu(B*sc+sh), sc/sh computed inline from prev-layer stats+gamma/beta.
// TRANSC: smem-staged transposed C. STATS/RS/BIAS: epilogue features.
// statoff selects the stats parity buffer for zstats/STATS.
#define AFL 4096
#define BFL 2048
#define O_B  8192
#define O_B2 12288

template<int SPLITA, int COMBINE, int BNB, int TRANSC, int STATS, int RS, int BIAS>
__global__ void __launch_bounds__(256, 3)
k_mma2(const float* __restrict__ Ag, const float* __restrict__ Bg,
       float* __restrict__ Cg,
       const float* __restrict__ rowscale, const float* __restrict__ bias,
       const float* __restrict__ rowscaleB, long bOff2,
       const float* __restrict__ pSum, const float* __restrict__ pSq,
       const float* __restrict__ pGam, const float* __restrict__ pBet,
       int statoff,
       int K, int lda, int ldb, int N, int M,
       long sA, long sB, long sC, int zstats,
       int koffY, long cOffY) {
    extern __shared__ float sm[];
    uint32_t sbase = smem_u32(sm);

    int tid = threadIdx.x, lane = tid & 31, wid = tid >> 5;
    int wm = wid >> 2, wn = wid & 3;           // 2 x 4 warp grid, warp tile 64x16
    int col0 = blockIdx.x * 64;
    int row0, k_base;
    long cadd;
    if (koffY) { row0 = 0; k_base = blockIdx.y * koffY; cadd = (long)blockIdx.y * cOffY; }
    else       { row0 = blockIdx.y * 128; k_base = 0; cadd = 0; }
    int z = blockIdx.z;

    if (zstats && blockIdx.y == 0 && tid < 64) {
        g_sum[statoff + z * Hh + col0 + tid] = 0.f;
        g_sq [statoff + z * Hh + col0 + tid] = 0.f;
    }

    const float* A  = Ag + (size_t)z * sA + k_base;
    const float* B  = Bg + (size_t)z * sB + k_base;
    const float* B2 = COMBINE ? (Bg + bOff2 + (size_t)z * sB + k_base) : nullptr;
    float* C = Cg + (size_t)z * sC + cadd;

    int cr = tid >> 3;                 // 0..31
    int cc = (tid & 7) * 4;

    float acc[4][2][4];
#pragma unroll
    for (int i = 0; i < 4; i++)
#pragma unroll
        for (int j = 0; j < 2; j++)
#pragma unroll
            for (int q = 0; q < 4; q++) acc[i][j][q] = 0.f;

    int nkb = K >> 5;
    int g = lane >> 2, t = lane & 3;

    float rsB[2], bAc[2], bBc[2];
    if (COMBINE) {
#pragma unroll
        for (int nf = 0; nf < 2; nf++)
            rsB[nf] = rowscaleB[(size_t)z * Mm + col0 + wn * 16 + nf * 8 + g];
    }
    if (BNB) {
#pragma unroll
        for (int nf = 0; nf < 2; nf++) {
            int h = col0 + wn * 16 + nf * 8 + g;
            bn_params(pSum[z*Hh + h], pSq[z*Hh + h], pGam[h], pBet[h], bAc[nf], bBc[nf]);
        }
    }

    // ldmatrix per-lane addressing
    int lrow = lane & 7;
    int lsub = lane >> 3;
    uint32_t rm4  = (uint32_t)lrow << 4;
    uint32_t cb4A = (uint32_t)(lsub >> 1) << 4;
    uint32_t cb4B = (uint32_t)(lsub & 1) << 4;
    uint32_t aAddr[4], bAddr;
#pragma unroll
    for (int mf = 0; mf < 4; mf++)
        aAddr[mf] = sbase + (uint32_t)((wm * 64 + mf * 16 + ((lsub & 1) << 3) + lrow) << 7);
    bAddr = sbase + O_B * 4 + (uint32_t)((wn * 16 + (lsub >> 1) * 8 + lrow) << 7);

#pragma unroll
    for (int s = 0; s < 2; s++) {
        int kk = s * 32;
#pragma unroll
        for (int i = 0; i < 4; i++) {             // A: 128 rows, 256 threads
            int rr = cr + i * 32;
            uint32_t so = (uint32_t)(s * AFL + rr * 32 + (cc ^ ((rr & 7) * 4))) * 4;
            CP16(sbase + so, A + (size_t)(row0 + rr) * lda + kk + cc);
        }
#pragma unroll
        for (int i = 0; i < 2; i++) {             // B: 64 rows
            int rr = cr + i * 32;
            uint32_t sw = (uint32_t)(rr * 32 + (cc ^ ((rr & 7) * 4)));
            size_t gb = (size_t)(col0 + rr) * ldb + kk + cc;
            CP16(sbase + (uint32_t)(O_B + s * BFL + sw) * 4, B + gb);
            if (COMBINE) CP16(sbase + (uint32_t)(O_B2 + s * BFL + sw) * 4, B2 + gb);
        }
        CPCOMMIT();
    }

    for (int kb = 0; kb < nkb; kb++) {
        int s = kb & 1;
        CPWAIT1();
        __syncthreads();
        uint32_t aOffS = (uint32_t)(s * AFL) * 4;
        uint32_t bOffS = (uint32_t)(s * BFL) * 4;

#pragma unroll
        for (int ks = 0; ks < 4; ks++) {
            uint32_t ka  = (((uint32_t)ks << 5) + cb4A) ^ rm4;
            uint32_t kbo = (((uint32_t)ks << 5) + cb4B) ^ rm4;
            uint32_t a[4][4], bR[2][2], bl[2][2];
#pragma unroll
            for (int mf = 0; mf < 4; mf++)
                ldsm4(a[mf], aAddr[mf] + aOffS + ka);
            {
                uint32_t r[4];
                ldsm4(r, bAddr + bOffS + kbo);
                bR[0][0] = r[0]; bR[0][1] = r[1]; bR[1][0] = r[2]; bR[1][1] = r[3];
            }
            if (COMBINE) {
                uint32_t r[4];
                ldsm4(r, bAddr + (O_B2 - O_B) * 4 + bOffS + kbo);
#pragma unroll
                for (int nf = 0; nf < 2; nf++)
#pragma unroll
                    for (int q = 0; q < 2; q++) {
                        float u = (__uint_as_float(bR[nf][q]) + __uint_as_float(r[nf*2+q])) * rsB[nf];
                        bR[nf][q] = __float_as_uint(u);
                    }
            }
            if (BNB) {
#pragma unroll
                for (int nf = 0; nf < 2; nf++)
#pragma unroll
                    for (int q = 0; q < 2; q++) {
                        float u = fmaxf(fmaf(__uint_as_float(bR[nf][q]), bAc[nf], bBc[nf]), 0.f);
                        bR[nf][q] = __float_as_uint(u);
                    }
            }
#pragma unroll
            for (int nf = 0; nf < 2; nf++) {
                bl[nf][0] = lo_tf32(bR[nf][0]);
                bl[nf][1] = lo_tf32(bR[nf][1]);
            }
#pragma unroll
            for (int mf = 0; mf < 4; mf++)
#pragma unroll
                for (int nf = 0; nf < 2; nf++)
                    mma_tf32(acc[mf][nf], a[mf], bR[nf]);
#pragma unroll
            for (int mf = 0; mf < 4; mf++)
#pragma unroll
                for (int nf = 0; nf < 2; nf++)
                    mma_tf32(acc[mf][nf], a[mf], bl[nf]);
            if (SPLITA) {
                uint32_t al[4][4];
#pragma unroll
                for (int mf = 0; mf < 4; mf++)
#pragma unroll
                    for (int q = 0; q < 4; q++)
                        al[mf][q] = lo_tf32(a[mf][q]);
#pragma unroll
                for (int mf = 0; mf < 4; mf++)
#pragma unroll
                    for (int nf = 0; nf < 2; nf++)
                        mma_tf32(acc[mf][nf], al[mf], bR[nf]);
            }
        }
        __syncthreads();

        if (kb + 2 < nkb) {
            int kk = (kb + 2) * 32;
#pragma unroll
            for (int i = 0; i < 4; i++) {
                int rr = cr + i * 32;
                uint32_t so = (uint32_t)(s * AFL + rr * 32 + (cc ^ ((rr & 7) * 4))) * 4;
                CP16(sbase + so, A + (size_t)(row0 + rr) * lda + kk + cc);
            }
#pragma unroll
            for (int i = 0; i < 2; i++) {
                int rr = cr + i * 32;
                uint32_t sw = (uint32_t)(rr * 32 + (cc ^ ((rr & 7) * 4)));
                size_t gb = (size_t)(col0 + rr) * ldb + kk + cc;
                CP16(sbase + (uint32_t)(O_B + s * BFL + sw) * 4, B + gb);
                if (COMBINE) CP16(sbase + (uint32_t)(O_B2 + s * BFL + sw) * 4, B2 + gb);
            }
        }
        CPCOMMIT();
    }

    // ---------------- epilogue ----------------
    const float* rsb = RS ? (rowscale + (size_t)z * M) : nullptr;
    float cs[STATS ? 4 : 1], cq[STATS ? 4 : 1];
    if (STATS) {
#pragma unroll
        for (int i = 0; i < 4; i++) { cs[i] = 0.f; cq[i] = 0.f; }
    }
    if (TRANSC) __syncthreads();

#pragma unroll
    for (int mf = 0; mf < 4; mf++) {
        int rl = wm * 64 + mf * 16 + g;
        int rr = row0 + rl;
        float rs0 = RS ? rsb[rr]     : 1.f;
        float rs1 = RS ? rsb[rr + 8] : 1.f;
#pragma unroll
        for (int nf = 0; nf < 2; nf++) {
            int cl  = wn * 16 + nf * 8 + t * 2;
            int ccg = col0 + cl;
            float c0 = acc[mf][nf][0] * rs0, c1 = acc[mf][nf][1] * rs0;
            float c2 = acc[mf][nf][2] * rs1, c3 = acc[mf][nf][3] * rs1;
            if (BIAS) {
                float b0 = bias[ccg], b1 = bias[ccg + 1];
                c0 += b0; c1 += b1; c2 += b0; c3 += b1;
            }
            if (STATS) {
                cs[nf*2]   += c0 + c2;  cs[nf*2+1] += c1 + c3;
                cq[nf*2]   += c0*c0 + c2*c2;
                cq[nf*2+1] += c1*c1 + c3*c3;
            }
            if (TRANSC) {
                sm[cl       * 132 + rl    ] = c0;
                sm[(cl + 1) * 132 + rl    ] = c1;
                sm[cl       * 132 + rl + 8] = c2;
                sm[(cl + 1) * 132 + rl + 8] = c3;
            } else {
                *reinterpret_cast<float2*>(&C[(size_t)rr * N + ccg])       = make_float2(c0, c1);
                *reinterpret_cast<float2*>(&C[(size_t)(rr + 8) * N + ccg]) = make_float2(c2, c3);
            }
        }
    }
    if (TRANSC) {
        __syncthreads();
        for (int i = tid; i < 64 * 32; i += 256) {
            int h  = i >> 5;
            int n4 = (i & 31) << 2;
            float4 v = *reinterpret_cast<float4*>(&sm[h * 132 + n4]);
            *reinterpret_cast<float4*>(&C[(size_t)(col0 + h) * N + row0 + n4]) = v;
        }
    }
    if (STATS) {
#pragma unroll
        for (int off = 4; off <= 16; off <<= 1) {
#pragma unroll
            for (int i = 0; i < 4; i++) {
                cs[i] += __shfl_xor_sync(0xffffffffu, cs[i], off);
                cq[i] += __shfl_xor_sync(0xffffffffu, cq[i], off);
            }
        }
        if (g == 0) {
#pragma unroll
            for (int nf = 0; nf < 2; nf++) {
#pragma unroll
                for (int j = 0; j < 2; j++) {
                    int ccg = col0 + wn * 16 + nf * 8 + t * 2 + j;
                    atomicAdd(&g_sum[statoff + z * Hh + ccg], cs[nf*2+j]);
                    atomicAdd(&g_sq [statoff + z * Hh + ccg], cq[nf*2+j]);
                }
            }
        }
    }
}

// ---------------- encoder ----------------
__global__ void k_encoder(const float* __restrict__ obs,
                          const float* __restrict__ Wenc,
                          const float* __restrict__ benc) {
    int bn = blockIdx.x;
    int h  = threadIdx.x;
    int b  = bn >> 9, n = bn & (Nn - 1);
    __shared__ float srow[Tt*DINd];
    if (h < Tt*DINd) srow[h] = obs[bn*Tt*DINd + h];
    __syncthreads();
    float w0 = Wenc[h], w1 = Wenc[Hh + h], bb = benc[h];
    float acc = 0.f;
#pragma unroll
    for (int t = 0; t < Tt; t++) {
        float v = fmaf(srow[2*t], w0, fmaf(srow[2*t+1], w1, bb));
        acc += fmaxf(v, 0.f);
    }
    float r = acc * (1.f / Tt);
    g_h[(size_t)bn*Hh + h] = r;
    g_hsT[((size_t)b*Hh + h)*Nn + n] = r;
}

// ---------------- incidence build (raw counts) ----------------
__global__ void k_zero_dense() {
    int i = blockIdx.x * blockDim.x + threadIdx.x;
    g_Hc[i]  = 0.f;
    g_HcT[i] = 0.f;
    if (i < Bn*Mm) g_cntm[i] = 0;
    if (i < Bn*Nn) g_cntn[i] = 0;
}
__global__ void k_build(const int* __restrict__ idx) {
    int i = blockIdx.x * blockDim.x + threadIdx.x;
    int b = i >> 13, e = i & (Ee - 1);
    int n = idx[b*2*Ee + e];
    int m = idx[b*2*Ee + Ee + e];
    atomicAdd(&g_Hc [((size_t)b*Nn + n)*Mm + m], 1.f);
    atomicAdd(&g_HcT[((size_t)b*Mm + m)*Nn + n], 1.f);
    atomicAdd(&g_cntn[b*Nn + n], 1);
    atomicAdd(&g_cntm[b*Mm + m], 1);
}
__global__ void k_invdeg() {
    int i = blockIdx.x * blockDim.x + threadIdx.x;
    if (i < Bn*Mm) g_invb[i] = 1.f / fmaxf((float)g_cntm[i], 1.f);
    if (i < Bn*Nn) g_invd[i] = 1.f / fmaxf((float)g_cntn[i], 1.f);
}

// ---------------- theta transpose ----------------
__global__ void k_trans_theta(const float* __restrict__ thetas) {
    __shared__ float t[32][33];
    int l  = blockIdx.z;
    int x0 = blockIdx.x * 32, y0 = blockIdx.y * 32;
    int tx = threadIdx.x, ty = threadIdx.y;
    const float* src = thetas + (size_t)l * Hh * Hh;
#pragma unroll
    for (int j = 0; j < 4; j++)
        t[ty + j*8][tx] = src[(size_t)(y0 + ty + j*8)*Hh + x0 + tx];
    __syncthreads();
#pragma unroll
    for (int j = 0; j < 4; j++)
        g_thT[(size_t)l*Hh*Hh + (size_t)(x0 + ty + j*8)*Hh + y0 + tx] = t[tx][ty + j*8];
}

// ---------------- fused tail: out = (h + relu(BN(hcT))) @ Wdec + bdec ----------------
// One block = 32 nodes of one batch. Dynamic smem: xs[32][257] + Ws[256*24].
__global__ void __launch_bounds__(256)
k_bn_dec(const float* __restrict__ gam, const float* __restrict__ bet,
         const float* __restrict__ Wdec, const float* __restrict__ bdec,
         float* __restrict__ out, int statoff) {
    extern __shared__ float dsm[];
    float* xs = dsm;                    // [32][257]
    float* Ws = dsm + 32 * 257;         // [256*24]
    __shared__ float ssc[Hh], ssh[Hh];
    int tid = threadIdx.x;
    int b = blockIdx.y, n0 = blockIdx.x * 32;

    {   // per-h BN params
        int h = tid;
        bn_params(g_sum[statoff + b*Hh + h], g_sq[statoff + b*Hh + h],
                  gam[h], bet[h], ssc[h], ssh[h]);
    }
    for (int i = tid; i < Hh * Pout; i += 256) Ws[i] = Wdec[i];
    __syncthreads();

    // hcT pass: tx = node (0..31), ty = h-subgroup (0..7); coalesced along n
    int tx = tid & 31, ty = tid >> 5;
    const float* hcb = g_hcT + (size_t)b * Hh * Nn + n0 + tx;
#pragma unroll
    for (int hb = 0; hb < Hh; hb += 8) {
        int h = hb + ty;
        float v = hcb[(size_t)h * Nn];
        xs[tx * 257 + h] = fmaxf(fmaf(v, ssc[h], ssh[h]), 0.f);
    }
    __syncthreads();
    // add residual h (coalesced along h)
    for (int i = tid; i < 32 * Hh; i += 256) {
        int n = i >> 8, h = i & (Hh - 1);
        xs[n * 257 + h] += g_h[((size_t)b * Nn + n0 + n) * Hh + h];
    }
    __syncthreads();

    // decoder: warp w handles nodes w*4 .. w*4+3
    int lane = tid & 31, wid = tid >> 5;
    int wl = (lane < Pout) ? lane : 0;
#pragma unroll
    for (int r = 0; r < 4; r++) {
        int row = wid * 4 + r;
        const float* xr_s = xs + row * 257;
        float xr[8];
#pragma unroll
        for (int j = 0; j < 8; j++) xr[j] = xr_s[lane + j * 32];
        float acc = 0.f;
#pragma unroll 4
        for (int k = 0; k < Hh; k++) {
            float xv = __shfl_sync(0xffffffffu, xr[k >> 5], k & 31);
            acc = fmaf(xv, Ws[k * Pout + wl], acc);
        }
        if (lane < Pout)
            out[((size_t)b * Nn + n0 + row) * Pout + lane] = acc + bdec[lane];
    }
}

// ---------------- launch ----------------
extern "C" void kernel_launch(void* const* d_in, const int* in_sizes, int n_in,
                              void* d_out, int out_size) {
    const float* obs    = (const float*)d_in[0];
    const int*   idx    = (const int*)  d_in[1];
    const float* Wenc   = (const float*)d_in[2];
    const float* benc   = (const float*)d_in[3];
    const float* thetas = (const float*)d_in[4];
    const float* cbias  = (const float*)d_in[5];
    const float* gam    = (const float*)d_in[6];
    const float* bet    = (const float*)d_in[7];
    const float* Wdec   = (const float*)d_in[8];
    const float* bdec   = (const float*)d_in[9];
    float* out = (float*)d_out;

    float *dHc, *dHcT, *dhsT, *dhcT, *dYp, *dZT, *dthT, *dinvb, *dinvd, *dsum, *dsq;
    cudaGetSymbolAddress((void**)&dHc,   g_Hc);
    cudaGetSymbolAddress((void**)&dHcT,  g_HcT);
    cudaGetSymbolAddress((void**)&dhsT,  g_hsT);
    cudaGetSymbolAddress((void**)&dhcT,  g_hcT);
    cudaGetSymbolAddress((void**)&dYp,   g_Yp);
    cudaGetSymbolAddress((void**)&dZT,   g_ZT);
    cudaGetSymbolAddress((void**)&dthT,  g_thT);
    cudaGetSymbolAddress((void**)&dinvb, g_invb);
    cudaGetSymbolAddress((void**)&dinvd, g_invd);
    cudaGetSymbolAddress((void**)&dsum,  g_sum);
    cudaGetSymbolAddress((void**)&dsq,   g_sq);

    const int SMEM_G = (2*AFL + 2*BFL) * 4;   // 48KB
    const int SMEM_C = (2*AFL + 4*BFL) * 4;   // 64KB (COMBINE)
    const int SMEM_D = (32 * 257 + Hh * Pout) * 4;  // k_bn_dec ~57.5KB
    cudaFuncSetAttribute((const void*)k_mma2<0,0,0,0,0,0,0>, cudaFuncAttributeMaxDynamicSharedMemorySize, SMEM_G);
    cudaFuncSetAttribute((const void*)k_mma2<0,0,1,0,0,0,0>, cudaFuncAttributeMaxDynamicSharedMemorySize, SMEM_G);
    cudaFuncSetAttribute((const void*)k_mma2<1,1,0,0,0,0,0>, cudaFuncAttributeMaxDynamicSharedMemorySize, SMEM_C);
    cudaFuncSetAttribute((const void*)k_mma2<0,0,0,1,1,1,1>, cudaFuncAttributeMaxDynamicSharedMemorySize, SMEM_G);
    cudaFuncSetAttribute((const void*)k_bn_dec, cudaFuncAttributeMaxDynamicSharedMemorySize, SMEM_D);

    k_encoder<<<Bn*Nn, Hh>>>(obs, Wenc, benc);
    k_zero_dense<<<Bn*Nn*Mm/256, 256>>>();
    k_build<<<Bn*Ee/256, 256>>>(idx);

    for (int l = 0; l < Ll; l++) {
        int soff  = (l & 1) * Bn * Hh;
        int spoff = ((l - 1) & 1) * Bn * Hh;
        // S1 split-K (zeroes this layer's stats): Yp[y] = HcT @ Bsrc^T over K-slice y
        if (l == 0) {
            k_mma2<0,0,0,0,0,0,0><<<dim3(4, 2, Bn), 256, SMEM_G>>>(dHcT, dhsT, dYp,
                nullptr, nullptr, nullptr, 0L,
                nullptr, nullptr, nullptr, nullptr, soff,
                256, Nn, Nn, Hh, Mm,
                (long)Mm*Nn, (long)Hh*Nn, (long)Mm*Hh, 1, 256, (long)Bn*Mm*Hh);
            k_invdeg<<<(Bn*Nn + 255)/256, 256>>>();
            k_trans_theta<<<dim3(Hh/32, Hh/32, Ll), dim3(32, 8)>>>(thetas);
        } else {
            k_mma2<0,0,1,0,0,0,0><<<dim3(4, 2, Bn), 256, SMEM_G>>>(dHcT, dhcT, dYp,
                nullptr, nullptr, nullptr, 0L,
                dsum + spoff, dsq + spoff, gam + (size_t)(l-1)*Hh, bet + (size_t)(l-1)*Hh, soff,
                256, Nn, Nn, Hh, Mm,
                (long)Mm*Nn, (long)Hh*Nn, (long)Mm*Hh, 1, 256, (long)Bn*Mm*Hh);
        }
        // S2: ZT[b](256x128) = thT_l @ [invb*(Yp0+Yp1)]^T
        k_mma2<1,1,0,0,0,0,0><<<dim3(2, 2, Bn), 256, SMEM_C>>>(dthT + (size_t)l*Hh*Hh, dYp, dZT,
            nullptr, nullptr, dinvb, (long)Bn*Mm*Hh,
            nullptr, nullptr, nullptr, nullptr, 0,
            256, Hh, Hh, Mm, Hh,
            0L, (long)Mm*Hh, (long)Hh*Mm, 0, 0, 0L);
        // S3: hcT = (Dinv*(Hc @ ZT^T) + bias)^T, fused BN stats, transposed write
        k_mma2<0,0,0,1,1,1,1><<<dim3(4, 4, Bn), 256, SMEM_G>>>(dHc, dZT, dhcT,
            dinvd, cbias + (size_t)l*Hh, nullptr, 0L,
            nullptr, nullptr, nullptr, nullptr, soff,
            128, Mm, Mm, Nn, Nn,
            (long)Nn*Mm, (long)Hh*Mm, (long)Hh*Nn, 0, 0, 0L);
    }

    k_bn_dec<<<dim3(Nn/32, Bn), 256, SMEM_D>>>(
        gam + (size_t)(Ll-1)*Hh, bet + (size_t)(Ll-1)*Hh, Wdec, bdec, out,
        ((Ll-1) & 1) * Bn * Hh);
}